// round 3
// baseline (speedup 1.0000x reference)
#include <cuda_runtime.h>

#define BATCH 8
#define MDIM 256
#define NDIM 256
#define WID 64
#define MODES 16
#define NLAYERS 4

// ---------------- scratch (static device arrays; no allocations) -------------
__device__ float  g_h [BATCH*MDIM*NDIM*WID];        // 134 MB  [b][m][n][c]
__device__ float2 g_t1[BATCH*MDIM*MODES*WID];       // 16.8 MB [b][m][ky][c]
__device__ float2 g_X [512*BATCH*WID];              // 2.1 MB  [p][b][c]
__device__ float2 g_Y [512*BATCH*WID];              // 2.1 MB  [p][b][o]
__device__ float2 g_G [BATCH*MDIM*MODES*WID];       // 16.8 MB [b][m][ky][o]
__device__ float2 g_tw[256];                        // e^{2*pi*i*k/256}

// p in [0,512): p = half*256 + kx_local*16 + ky ; half=0 -> kx=kx_local,
// half=1 -> kx = 240+kx_local.

// ---------------- twiddle table ----------------------------------------------
__global__ void k_twiddle() {
    int k = threadIdx.x;
    float a = (float)k / 128.0f;          // 2*pi*k/256 = pi * k/128
    g_tw[k] = make_float2(cospif(a), sinpif(a));
}

// ---------------- input projection -------------------------------------------
__global__ void k_inproj(const float* __restrict__ x,
                         const float* __restrict__ in_w,
                         const float* __restrict__ in_b) {
    int idx = blockIdx.x * blockDim.x + threadIdx.x;   // over B*M*N*64
    int c   = idx & 63;
    int pix = idx >> 6;
    int n = pix & 255;
    int m = (pix >> 8) & 255;
    const float* xp = x + (size_t)pix * 3;
    float pm = -1.0f + ((float)m + 0.5f) * (2.0f / 256.0f);
    float pn = -1.0f + ((float)n + 0.5f) * (2.0f / 256.0f);
    float acc = in_b[c];
    acc += xp[0] * in_w[0 * WID + c];
    acc += xp[1] * in_w[1 * WID + c];
    acc += xp[2] * in_w[2 * WID + c];
    acc += pm    * in_w[3 * WID + c];
    acc += pn    * in_w[4 * WID + c];
    g_h[idx] = acc;
}

// ---------------- forward DFT along n (h -> T1) -------------------------------
// block = (b,m) : 2048 blocks x 256 thr.  T1[bm][ky][c] = sum_n h[n][c] e^{-i th}
__global__ void k_f1() {
    int bm = blockIdx.x;
    __shared__ float2 tw[256];
    __shared__ float2 red[4][MODES][WID];     // 32 KB
    int tid = threadIdx.x;
    tw[tid] = g_tw[tid];
    __syncthreads();
    int c = tid & 63, part = tid >> 6;
    const float* hp = g_h + (size_t)bm * NDIM * WID + c;
    float ar[MODES], ai[MODES];
#pragma unroll
    for (int k = 0; k < MODES; k++) { ar[k] = 0.f; ai[k] = 0.f; }
    for (int nn = 0; nn < 64; nn++) {
        int n = part * 64 + nn;
        float v = hp[(size_t)n * WID];
#pragma unroll
        for (int ky = 0; ky < MODES; ky++) {
            float2 t = tw[(ky * n) & 255];
            ar[ky] += v * t.x;
            ai[ky] -= v * t.y;
        }
    }
#pragma unroll
    for (int k = 0; k < MODES; k++) red[part][k][c] = make_float2(ar[k], ai[k]);
    __syncthreads();
    for (int i = tid; i < MODES * WID; i += 256) {
        int ky = i >> 6, cc = i & 63;
        float2 a = red[0][ky][cc], b = red[1][ky][cc];
        float2 d = red[2][ky][cc], e = red[3][ky][cc];
        g_t1[(size_t)bm * MODES * WID + i] =
            make_float2(a.x + b.x + d.x + e.x, a.y + b.y + d.y + e.y);
    }
}

// ---------------- forward DFT along m (T1 -> X) -------------------------------
// block = b*32 + ky*2 + half : 256 blocks x 256 thr
__global__ void k_f2() {
    int bi = blockIdx.x;
    int half = bi & 1;
    int ky   = (bi >> 1) & 15;
    int b    = bi >> 5;
    __shared__ float2 tw[256];
    __shared__ float2 red[4][16][WID];        // 32 KB
    int tid = threadIdx.x;
    tw[tid] = g_tw[tid];
    __syncthreads();
    int c = tid & 63, part = tid >> 6;
    const float2* tp = g_t1 + ((size_t)(b * MDIM) * MODES + ky) * WID + c;
    float ar[16], ai[16];
#pragma unroll
    for (int j = 0; j < 16; j++) { ar[j] = 0.f; ai[j] = 0.f; }
    int kbase = half ? 240 : 0;
    for (int mm = 0; mm < 64; mm++) {
        int m = part * 64 + mm;
        float2 t = tp[(size_t)m * MODES * WID];
#pragma unroll
        for (int j = 0; j < 16; j++) {
            float2 w = tw[((kbase + j) * m) & 255];
            ar[j] += t.x * w.x + t.y * w.y;   // T1 * e^{-i th}
            ai[j] += t.y * w.x - t.x * w.y;
        }
    }
#pragma unroll
    for (int j = 0; j < 16; j++) red[part][j][c] = make_float2(ar[j], ai[j]);
    __syncthreads();
    for (int i = tid; i < 16 * WID; i += 256) {
        int j = i >> 6, cc = i & 63;
        float2 a = red[0][j][cc], b2 = red[1][j][cc];
        float2 d = red[2][j][cc], e = red[3][j][cc];
        int p = half * 256 + j * 16 + ky;
        g_X[((size_t)p * 8 + b) * WID + cc] =
            make_float2(a.x + b2.x + d.x + e.x, a.y + b2.y + d.y + e.y);
    }
}

// ---------------- spectral mixing (X -> Y) ------------------------------------
// block = p : 512 blocks x 256 thr.  Y[p][b][o] = sum_i X[p][b][i]*W_p[i][o]
__global__ void k_mix(const float* __restrict__ fw1,
                      const float* __restrict__ fw2, int layer) {
    int p = blockIdx.x;
    __shared__ float2 W [64][64];   // 32 KB
    __shared__ float2 Xs[8][64];    //  4 KB
    int tid = threadIdx.x;
    const float* fw = (p < 256) ? fw1 : fw2;
    int pq = p & 255;               // kx_local*16 + ky  == last-two-dims index
    size_t base = ((size_t)layer * 64 * 64 * 256 + pq) * 2;
    for (int k = tid; k < 4096; k += 256) {
        int i = k >> 6, o = k & 63;
        size_t s = base + (size_t)(i * 64 + o) * 512;
        W[i][o] = make_float2(fw[s], fw[s + 1]);
    }
    for (int k = tid; k < 512; k += 256)
        Xs[k >> 6][k & 63] = g_X[(size_t)p * 512 + k];
    __syncthreads();
#pragma unroll
    for (int rep = 0; rep < 2; rep++) {
        int idx = tid + rep * 256;
        int b = idx >> 6, o = idx & 63;
        float accr = 0.f, acci = 0.f;
#pragma unroll
        for (int i = 0; i < 64; i++) {
            float2 xv = Xs[b][i];
            float2 wv = W[i][o];
            accr += xv.x * wv.x - xv.y * wv.y;
            acci += xv.x * wv.y + xv.y * wv.x;
        }
        g_Y[(size_t)p * 512 + idx] = make_float2(accr, acci);
    }
}

// ---------------- inverse DFT along kx (Y -> G) -------------------------------
// block = b*64 + ky*4 + quad : 512 blocks x 256 thr
__global__ void k_i1() {
    int bi = blockIdx.x;
    int quad = bi & 3;
    int ky   = (bi >> 2) & 15;
    int b    = bi >> 6;
    __shared__ float2 tw[256];
    __shared__ float2 Ys[32][64];   // 16 KB
    int tid = threadIdx.x;
    tw[tid] = g_tw[tid];
    for (int k = tid; k < 2048; k += 256) {
        int j = k >> 6, o = k & 63;
        int half = j >> 4, jl = j & 15;
        int p = half * 256 + jl * 16 + ky;
        Ys[j][o] = g_Y[((size_t)p * 8 + b) * 64 + o];
    }
    __syncthreads();
    int o = tid & 63, msub = tid >> 6;
    for (int it = 0; it < 16; it++) {
        int m = quad * 64 + it * 4 + msub;
        float sr = 0.f, si = 0.f;
#pragma unroll
        for (int j = 0; j < 32; j++) {
            int kx = (j < 16) ? j : (224 + j);   // 240..255 for high band
            float2 w = tw[(kx * m) & 255];
            float2 v = Ys[j][o];
            sr += v.x * w.x - v.y * w.y;         // Y * e^{+i th}
            si += v.x * w.y + v.y * w.x;
        }
        g_G[(((size_t)b * 256 + m) * 16 + ky) * 64 + o] = make_float2(sr, si);
    }
}

// ---------------- inverse DFT along n + pointwise GEMM + ReLU (G -> h) --------
// block = (b,m) : 2048 blocks x 256 thr.  4x4 register-tiled GEMM.
__global__ void k_i2(const float* __restrict__ lin_w,
                     const float* __restrict__ lin_b, int layer) {
    int bm = blockIdx.x;
    __shared__ float2 tw[256];
    __shared__ float2 Gs[16][64];   // 8 KB (pre-scaled)
    __shared__ float  lw[64][64];   // 16 KB [j][o]
    __shared__ float  lb[64];
    __shared__ float  ys[64][65];   // padded vs bank conflicts
    int tid = threadIdx.x;
    tw[tid] = g_tw[tid];
    for (int k = tid; k < 1024; k += 256) {
        int ky = k >> 6, o = k & 63;
        float s = (ky == 0 ? 1.0f : 2.0f) * (1.0f / 65536.0f);
        float2 v = g_G[(size_t)bm * 1024 + k];
        Gs[ky][o] = make_float2(v.x * s, v.y * s);
    }
    for (int k = tid; k < 4096; k += 256)
        lw[k >> 6][k & 63] = lin_w[(size_t)layer * 4096 + k];
    if (tid < 64) lb[tid] = lin_b[layer * 64 + tid];
    __syncthreads();
    int tx = tid & 15, ty = tid >> 4;   // o-quad / n-group
    float* hout = g_h + (size_t)bm * NDIM * WID;
    for (int rnd = 0; rnd < 4; rnd++) {
        float yv[4][4];
#pragma unroll
        for (int k = 0; k < 4; k++) {
            int n = rnd * 64 + ty * 4 + k;
            float y0 = 0.f, y1 = 0.f, y2 = 0.f, y3 = 0.f;
#pragma unroll
            for (int ky = 0; ky < 16; ky++) {
                float2 w = tw[(ky * n) & 255];
                float4 ga = *(const float4*)&Gs[ky][tx * 4];
                float4 gb = *(const float4*)&Gs[ky][tx * 4 + 2];
                y0 += ga.x * w.x - ga.y * w.y;
                y1 += ga.z * w.x - ga.w * w.y;
                y2 += gb.x * w.x - gb.y * w.y;
                y3 += gb.z * w.x - gb.w * w.y;
            }
            yv[k][0] = y0; yv[k][1] = y1; yv[k][2] = y2; yv[k][3] = y3;
            ys[ty * 4 + k][tx * 4 + 0] = y0;
            ys[ty * 4 + k][tx * 4 + 1] = y1;
            ys[ty * 4 + k][tx * 4 + 2] = y2;
            ys[ty * 4 + k][tx * 4 + 3] = y3;
        }
        __syncthreads();
        float acc[4][4];
#pragma unroll
        for (int k = 0; k < 4; k++)
#pragma unroll
            for (int q = 0; q < 4; q++) acc[k][q] = lb[tx * 4 + q];
#pragma unroll
        for (int j = 0; j < 64; j++) {
            float4 w4 = *(const float4*)&lw[j][tx * 4];
#pragma unroll
            for (int k = 0; k < 4; k++) {
                float yj = ys[ty * 4 + k][j];
                acc[k][0] += yj * w4.x;
                acc[k][1] += yj * w4.y;
                acc[k][2] += yj * w4.z;
                acc[k][3] += yj * w4.w;
            }
        }
#pragma unroll
        for (int k = 0; k < 4; k++) {
            int n = rnd * 64 + ty * 4 + k;
            float4 r;
            r.x = fmaxf(yv[k][0] + acc[k][0], 0.f);
            r.y = fmaxf(yv[k][1] + acc[k][1], 0.f);
            r.z = fmaxf(yv[k][2] + acc[k][2], 0.f);
            r.w = fmaxf(yv[k][3] + acc[k][3], 0.f);
            *(float4*)&hout[(size_t)n * WID + tx * 4] = r;
        }
        __syncthreads();
    }
}

// ---------------- output head: relu(h@W1+b1)@W2+b2 ---------------------------
// block = (b,m) : 2048 blocks x 256 thr.  4x4 tiles, warp-shuffle reduce.
__global__ void k_out(const float* __restrict__ out1_w,
                      const float* __restrict__ out1_b,
                      const float* __restrict__ out2_w,
                      const float* __restrict__ out2_b,
                      float* __restrict__ out) {
    int bm = blockIdx.x;
    __shared__ float hs [32][65];    // 8.3 KB
    __shared__ float w1s[64][128];   // 32 KB  [c][hidden]
    __shared__ float b1s[128];
    __shared__ float w2s[128];
    int tid = threadIdx.x;
    for (int k = tid; k < 8192; k += 256) w1s[k >> 7][k & 127] = out1_w[k];
    if (tid < 128) { b1s[tid] = out1_b[tid]; w2s[tid] = out2_w[tid]; }
    float b2 = out2_b[0];
    const float* hp = g_h + (size_t)bm * NDIM * WID;
    float* op = out + (size_t)bm * NDIM;
    int tx = tid & 31, ty = tid >> 5;   // hidden-quad / n-group
    for (int rnd = 0; rnd < 8; rnd++) {
        __syncthreads();
        for (int k = tid; k < 2048; k += 256)
            hs[k >> 6][k & 63] = hp[(size_t)rnd * 2048 + k];
        __syncthreads();
        float acc[4][4];
#pragma unroll
        for (int k = 0; k < 4; k++)
#pragma unroll
            for (int q = 0; q < 4; q++) acc[k][q] = b1s[tx * 4 + q];
#pragma unroll
        for (int j = 0; j < 64; j++) {
            float4 w4 = *(const float4*)&w1s[j][tx * 4];
#pragma unroll
            for (int k = 0; k < 4; k++) {
                float hv = hs[ty * 4 + k][j];
                acc[k][0] += hv * w4.x;
                acc[k][1] += hv * w4.y;
                acc[k][2] += hv * w4.z;
                acc[k][3] += hv * w4.w;
            }
        }
#pragma unroll
        for (int k = 0; k < 4; k++) {
            float part = fmaxf(acc[k][0], 0.f) * w2s[tx * 4 + 0]
                       + fmaxf(acc[k][1], 0.f) * w2s[tx * 4 + 1]
                       + fmaxf(acc[k][2], 0.f) * w2s[tx * 4 + 2]
                       + fmaxf(acc[k][3], 0.f) * w2s[tx * 4 + 3];
#pragma unroll
            for (int off = 16; off > 0; off >>= 1)
                part += __shfl_xor_sync(0xffffffffu, part, off);
            if (tx == 0) op[rnd * 32 + ty * 4 + k] = part + b2;
        }
    }
}

// ---------------- launch ------------------------------------------------------
extern "C" void kernel_launch(void* const* d_in, const int* in_sizes, int n_in,
                              void* d_out, int out_size) {
    const float* x      = (const float*)d_in[0];
    const float* in_w   = (const float*)d_in[1];
    const float* in_b   = (const float*)d_in[2];
    const float* fw1    = (const float*)d_in[3];
    const float* fw2    = (const float*)d_in[4];
    const float* lin_w  = (const float*)d_in[5];
    const float* lin_b  = (const float*)d_in[6];
    const float* out1_w = (const float*)d_in[7];
    const float* out1_b = (const float*)d_in[8];
    const float* out2_w = (const float*)d_in[9];
    const float* out2_b = (const float*)d_in[10];
    float* out = (float*)d_out;

    k_twiddle<<<1, 256>>>();
    k_inproj<<<(BATCH * MDIM * NDIM * WID) / 256, 256>>>(x, in_w, in_b);
    for (int l = 0; l < NLAYERS; l++) {
        k_f1 <<<BATCH * MDIM, 256>>>();
        k_f2 <<<BATCH * MODES * 2, 256>>>();
        k_mix<<<512, 256>>>(fw1, fw2, l);
        k_i1 <<<BATCH * MODES * 4, 256>>>();
        k_i2 <<<BATCH * MDIM, 256>>>(lin_w, lin_b, l);
    }
    k_out<<<BATCH * MDIM, 256>>>(out1_w, out1_b, out2_w, out2_b, out);
}

// round 9
// speedup vs baseline: 1.1628x; 1.1628x over previous
#include <cuda_runtime.h>

#define BATCH 8
#define MDIM 256
#define NDIM 256
#define WID 64
#define MODES 16
#define NLAYERS 4

// ---------------- scratch (static device arrays; no allocations) -------------
__device__ float  g_h [BATCH*MDIM*NDIM*WID];        // 134 MB  [b][m][n][c]
__device__ float2 g_t1[BATCH*MDIM*MODES*WID];       // 16.8 MB [b][m][ky][c]
__device__ float2 g_X [512*BATCH*WID];              // 2.1 MB  [p][b][c]
__device__ float2 g_Y [512*BATCH*WID];              // 2.1 MB  [p][b][o]
__device__ float2 g_G [BATCH*MDIM*MODES*WID];       // 16.8 MB [b][m][ky][o]
__device__ float2 g_tw[256];                        // e^{2*pi*i*k/256}

// ---------------- twiddle table ----------------------------------------------
__global__ void k_twiddle() {
    int k = threadIdx.x;
    float a = (float)k / 128.0f;          // 2*pi*k/256 = pi * k/128
    g_tw[k] = make_float2(cospif(a), sinpif(a));
}

// ---------------- input projection -------------------------------------------
__global__ void k_inproj(const float* __restrict__ x,
                         const float* __restrict__ in_w,
                         const float* __restrict__ in_b) {
    int idx = blockIdx.x * blockDim.x + threadIdx.x;   // over B*M*N*64
    int c   = idx & 63;
    int pix = idx >> 6;
    int n = pix & 255;
    int m = (pix >> 8) & 255;
    const float* xp = x + (size_t)pix * 3;
    float pm = -1.0f + ((float)m + 0.5f) * (2.0f / 256.0f);
    float pn = -1.0f + ((float)n + 0.5f) * (2.0f / 256.0f);
    float acc = in_b[c];
    acc += xp[0] * in_w[0 * WID + c];
    acc += xp[1] * in_w[1 * WID + c];
    acc += xp[2] * in_w[2 * WID + c];
    acc += pm    * in_w[3 * WID + c];
    acc += pn    * in_w[4 * WID + c];
    g_h[idx] = acc;
}

// ---------------- forward DFT along n (h -> T1)  [new: smem-staged] -----------
// block = (b,m): 2048 x 256. thread = (ky = tid>>4, cg = tid&15 -> 4 c's).
// Each thread owns the full 256-point sum: no reduction pass.
__global__ void k_f1() {
    int bm = blockIdx.x;
    __shared__ float2 tw[256];
    __shared__ float  hs[64][64];          // 16 KB chunk of h
    int tid = threadIdx.x;
    tw[tid] = g_tw[tid];
    int ky = tid >> 4, cg = tid & 15;
    const float4* hp4 = (const float4*)(g_h + (size_t)bm * NDIM * WID);
    float ar[4] = {0.f, 0.f, 0.f, 0.f}, ai[4] = {0.f, 0.f, 0.f, 0.f};
    for (int ch = 0; ch < 4; ch++) {
        int n0 = ch * 64;
        __syncthreads();
#pragma unroll
        for (int i = 0; i < 4; i++) {
            int f = tid + i * 256;                 // 1024 float4s
            int row = f >> 4, col4 = f & 15;
            float4 v = hp4[(size_t)(n0 + row) * 16 + col4];
            *(float4*)&hs[row][col4 * 4] = v;
        }
        __syncthreads();
#pragma unroll 8
        for (int nn = 0; nn < 64; nn++) {
            int n = n0 + nn;
            float2 t = tw[(ky * n) & 255];
            float4 hv = *(const float4*)&hs[nn][cg * 4];
            ar[0] += hv.x * t.x; ai[0] -= hv.x * t.y;
            ar[1] += hv.y * t.x; ai[1] -= hv.y * t.y;
            ar[2] += hv.z * t.x; ai[2] -= hv.z * t.y;
            ar[3] += hv.w * t.x; ai[3] -= hv.w * t.y;
        }
    }
    float4* op = (float4*)(g_t1 + (size_t)bm * MODES * WID + ky * 64 + cg * 4);
    op[0] = make_float4(ar[0], ai[0], ar[1], ai[1]);
    op[1] = make_float4(ar[2], ai[2], ar[3], ai[3]);
}

// ---------------- forward DFT along m (T1 -> X)  [new: 1024 blocks] -----------
// block = (b, ky, cchunk): 1024 x 256. thread = (j = tid>>3, cl = tid&7).
__global__ void k_f2() {
    int bi = blockIdx.x;
    int cchunk = bi & 7;
    int ky     = (bi >> 3) & 15;
    int b      = bi >> 7;
    __shared__ float2 tw[256];
    __shared__ float2 ts[64][8];           // 4 KB chunk of T1
    int tid = threadIdx.x;
    tw[tid] = g_tw[tid];
    int j = tid >> 3, cl = tid & 7;
    int c0 = cchunk * 8;
    int kx = (j < 16) ? j : (224 + j);     // 240..255 for high band
    float ar = 0.f, ai = 0.f;
    for (int ch = 0; ch < 4; ch++) {
        int m0 = ch * 64;
        __syncthreads();
#pragma unroll
        for (int i = 0; i < 2; i++) {
            int k = tid + i * 256;                 // 512 float2s
            int m = k >> 3, cc = k & 7;
            ts[m][cc] = g_t1[((size_t)((b * 256 + m0 + m) * 16 + ky)) * 64 + c0 + cc];
        }
        __syncthreads();
#pragma unroll 8
        for (int mm = 0; mm < 64; mm++) {
            int m = m0 + mm;
            float2 w = tw[(kx * m) & 255];
            float2 t = ts[mm][cl];
            ar += t.x * w.x + t.y * w.y;   // T1 * conj(w)
            ai += t.y * w.x - t.x * w.y;
        }
    }
    int p = (j < 16) ? (j * 16 + ky) : (256 + (j - 16) * 16 + ky);
    g_X[((size_t)p * 8 + b) * WID + c0 + cl] = make_float2(ar, ai);
}

// ---------------- spectral mixing (X -> Y)  [R3 known-good] -------------------
__global__ void k_mix(const float* __restrict__ fw1,
                      const float* __restrict__ fw2, int layer) {
    int p = blockIdx.x;
    __shared__ float2 W [64][64];   // 32 KB
    __shared__ float2 Xs[8][64];    //  4 KB
    int tid = threadIdx.x;
    const float* fw = (p < 256) ? fw1 : fw2;
    int pq = p & 255;               // kx_local*16 + ky
    size_t base = ((size_t)layer * 64 * 64 * 256 + pq) * 2;
    for (int k = tid; k < 4096; k += 256) {
        int i = k >> 6, o = k & 63;
        size_t s = base + (size_t)(i * 64 + o) * 512;
        W[i][o] = make_float2(fw[s], fw[s + 1]);
    }
    for (int k = tid; k < 512; k += 256)
        Xs[k >> 6][k & 63] = g_X[(size_t)p * 512 + k];
    __syncthreads();
#pragma unroll
    for (int rep = 0; rep < 2; rep++) {
        int idx = tid + rep * 256;
        int b = idx >> 6, o = idx & 63;
        float accr = 0.f, acci = 0.f;
#pragma unroll
        for (int i = 0; i < 64; i++) {
            float2 xv = Xs[b][i];
            float2 wv = W[i][o];
            accr += xv.x * wv.x - xv.y * wv.y;
            acci += xv.x * wv.y + xv.y * wv.x;
        }
        g_Y[(size_t)p * 512 + idx] = make_float2(accr, acci);
    }
}

// ---------------- inverse DFT along kx (Y -> G)  [R3 known-good] --------------
__global__ void k_i1() {
    int bi = blockIdx.x;
    int quad = bi & 3;
    int ky   = (bi >> 2) & 15;
    int b    = bi >> 6;
    __shared__ float2 tw[256];
    __shared__ float2 Ys[32][64];   // 16 KB
    int tid = threadIdx.x;
    tw[tid] = g_tw[tid];
    for (int k = tid; k < 2048; k += 256) {
        int j = k >> 6, o = k & 63;
        int half = j >> 4, jl = j & 15;
        int p = half * 256 + jl * 16 + ky;
        Ys[j][o] = g_Y[((size_t)p * 8 + b) * 64 + o];
    }
    __syncthreads();
    int o = tid & 63, msub = tid >> 6;
    for (int it = 0; it < 16; it++) {
        int m = quad * 64 + it * 4 + msub;
        float sr = 0.f, si = 0.f;
#pragma unroll
        for (int j = 0; j < 32; j++) {
            int kx = (j < 16) ? j : (224 + j);   // 240..255 for high band
            float2 w = tw[(kx * m) & 255];
            float2 v = Ys[j][o];
            sr += v.x * w.x - v.y * w.y;         // Y * e^{+i th}
            si += v.x * w.y + v.y * w.x;
        }
        g_G[(((size_t)b * 256 + m) * 16 + ky) * 64 + o] = make_float2(sr, si);
    }
}

// ---------------- inverse DFT along n + pointwise GEMM + ReLU  [R3] -----------
// block = (b,m) : 2048 blocks x 256 thr.  4x4 register-tiled GEMM.
__global__ void k_i2(const float* __restrict__ lin_w,
                     const float* __restrict__ lin_b, int layer) {
    int bm = blockIdx.x;
    __shared__ float2 tw[256];
    __shared__ float2 Gs[16][64];   // 8 KB (pre-scaled)
    __shared__ float  lw[64][64];   // 16 KB [j][o]
    __shared__ float  lb[64];
    __shared__ float  ys[64][65];   // padded vs bank conflicts
    int tid = threadIdx.x;
    tw[tid] = g_tw[tid];
    for (int k = tid; k < 1024; k += 256) {
        int ky = k >> 6, o = k & 63;
        float s = (ky == 0 ? 1.0f : 2.0f) * (1.0f / 65536.0f);
        float2 v = g_G[(size_t)bm * 1024 + k];
        Gs[ky][o] = make_float2(v.x * s, v.y * s);
    }
    for (int k = tid; k < 4096; k += 256)
        lw[k >> 6][k & 63] = lin_w[(size_t)layer * 4096 + k];
    if (tid < 64) lb[tid] = lin_b[layer * 64 + tid];
    __syncthreads();
    int tx = tid & 15, ty = tid >> 4;   // o-quad / n-group
    float* hout = g_h + (size_t)bm * NDIM * WID;
    for (int rnd = 0; rnd < 4; rnd++) {
        float yv[4][4];
#pragma unroll
        for (int k = 0; k < 4; k++) {
            int n = rnd * 64 + ty * 4 + k;
            float y0 = 0.f, y1 = 0.f, y2 = 0.f, y3 = 0.f;
#pragma unroll
            for (int ky = 0; ky < 16; ky++) {
                float2 w = tw[(ky * n) & 255];
                float4 ga = *(const float4*)&Gs[ky][tx * 4];
                float4 gb = *(const float4*)&Gs[ky][tx * 4 + 2];
                y0 += ga.x * w.x - ga.y * w.y;
                y1 += ga.z * w.x - ga.w * w.y;
                y2 += gb.x * w.x - gb.y * w.y;
                y3 += gb.z * w.x - gb.w * w.y;
            }
            yv[k][0] = y0; yv[k][1] = y1; yv[k][2] = y2; yv[k][3] = y3;
            ys[ty * 4 + k][tx * 4 + 0] = y0;
            ys[ty * 4 + k][tx * 4 + 1] = y1;
            ys[ty * 4 + k][tx * 4 + 2] = y2;
            ys[ty * 4 + k][tx * 4 + 3] = y3;
        }
        __syncthreads();
        float acc[4][4];
#pragma unroll
        for (int k = 0; k < 4; k++)
#pragma unroll
            for (int q = 0; q < 4; q++) acc[k][q] = lb[tx * 4 + q];
#pragma unroll
        for (int j = 0; j < 64; j++) {
            float4 w4 = *(const float4*)&lw[j][tx * 4];
#pragma unroll
            for (int k = 0; k < 4; k++) {
                float yj = ys[ty * 4 + k][j];
                acc[k][0] += yj * w4.x;
                acc[k][1] += yj * w4.y;
                acc[k][2] += yj * w4.z;
                acc[k][3] += yj * w4.w;
            }
        }
#pragma unroll
        for (int k = 0; k < 4; k++) {
            int n = rnd * 64 + ty * 4 + k;
            float4 r;
            r.x = fmaxf(yv[k][0] + acc[k][0], 0.f);
            r.y = fmaxf(yv[k][1] + acc[k][1], 0.f);
            r.z = fmaxf(yv[k][2] + acc[k][2], 0.f);
            r.w = fmaxf(yv[k][3] + acc[k][3], 0.f);
            *(float4*)&hout[(size_t)n * WID + tx * 4] = r;
        }
        __syncthreads();
    }
}

// ---------------- output head: relu(h@W1+b1)@W2+b2  [R3 known-good] -----------
// block = (b,m) : 2048 blocks x 256 thr.  4x4 tiles, warp-shuffle reduce.
__global__ void k_out(const float* __restrict__ out1_w,
                      const float* __restrict__ out1_b,
                      const float* __restrict__ out2_w,
                      const float* __restrict__ out2_b,
                      float* __restrict__ out) {
    int bm = blockIdx.x;
    __shared__ float hs [32][65];    // 8.3 KB
    __shared__ float w1s[64][128];   // 32 KB  [c][hidden]
    __shared__ float b1s[128];
    __shared__ float w2s[128];
    int tid = threadIdx.x;
    for (int k = tid; k < 8192; k += 256) w1s[k >> 7][k & 127] = out1_w[k];
    if (tid < 128) { b1s[tid] = out1_b[tid]; w2s[tid] = out2_w[tid]; }
    float b2 = out2_b[0];
    const float* hp = g_h + (size_t)bm * NDIM * WID;
    float* op = out + (size_t)bm * NDIM;
    int tx = tid & 31, ty = tid >> 5;   // hidden-quad / n-group
    for (int rnd = 0; rnd < 8; rnd++) {
        __syncthreads();
        for (int k = tid; k < 2048; k += 256)
            hs[k >> 6][k & 63] = hp[(size_t)rnd * 2048 + k];
        __syncthreads();
        float acc[4][4];
#pragma unroll
        for (int k = 0; k < 4; k++)
#pragma unroll
            for (int q = 0; q < 4; q++) acc[k][q] = b1s[tx * 4 + q];
#pragma unroll
        for (int j = 0; j < 64; j++) {
            float4 w4 = *(const float4*)&w1s[j][tx * 4];
#pragma unroll
            for (int k = 0; k < 4; k++) {
                float hv = hs[ty * 4 + k][j];
                acc[k][0] += hv * w4.x;
                acc[k][1] += hv * w4.y;
                acc[k][2] += hv * w4.z;
                acc[k][3] += hv * w4.w;
            }
        }
#pragma unroll
        for (int k = 0; k < 4; k++) {
            float part = fmaxf(acc[k][0], 0.f) * w2s[tx * 4 + 0]
                       + fmaxf(acc[k][1], 0.f) * w2s[tx * 4 + 1]
                       + fmaxf(acc[k][2], 0.f) * w2s[tx * 4 + 2]
                       + fmaxf(acc[k][3], 0.f) * w2s[tx * 4 + 3];
#pragma unroll
            for (int off = 16; off > 0; off >>= 1)
                part += __shfl_xor_sync(0xffffffffu, part, off);
            if (tx == 0) op[rnd * 32 + ty * 4 + k] = part + b2;
        }
    }
}

// ---------------- launch ------------------------------------------------------
extern "C" void kernel_launch(void* const* d_in, const int* in_sizes, int n_in,
                              void* d_out, int out_size) {
    const float* x      = (const float*)d_in[0];
    const float* in_w   = (const float*)d_in[1];
    const float* in_b   = (const float*)d_in[2];
    const float* fw1    = (const float*)d_in[3];
    const float* fw2    = (const float*)d_in[4];
    const float* lin_w  = (const float*)d_in[5];
    const float* lin_b  = (const float*)d_in[6];
    const float* out1_w = (const float*)d_in[7];
    const float* out1_b = (const float*)d_in[8];
    const float* out2_w = (const float*)d_in[9];
    const float* out2_b = (const float*)d_in[10];
    float* out = (float*)d_out;

    k_twiddle<<<1, 256>>>();
    k_inproj<<<(BATCH * MDIM * NDIM * WID) / 256, 256>>>(x, in_w, in_b);
    for (int l = 0; l < NLAYERS; l++) {
        k_f1 <<<BATCH * MDIM, 256>>>();
        k_f2 <<<BATCH * MODES * 8, 256>>>();
        k_mix<<<512, 256>>>(fw1, fw2, l);
        k_i1 <<<BATCH * MODES * 4, 256>>>();
        k_i2 <<<BATCH * MDIM, 256>>>(lin_w, lin_b, l);
    }
    k_out<<<BATCH * MDIM, 256>>>(out1_w, out1_b, out2_w, out2_b, out);
}

// round 10
// speedup vs baseline: 1.7227x; 1.4815x over previous
#include <cuda_runtime.h>

#define BATCH 8
#define MDIM 256
#define NDIM 256
#define WID 64
#define MODES 16
#define NLAYERS 4

// ---------------- scratch (static device arrays; no allocations) -------------
__device__ float  g_h [BATCH*MDIM*NDIM*WID];        // 134 MB  [b][m][n][c]
__device__ float2 g_t1[BATCH*MDIM*MODES*WID];       // 16.8 MB [b][m][ky][c]
__device__ float2 g_X [512*BATCH*WID];              // 2.1 MB  [p][b][c]
__device__ float2 g_Y [512*BATCH*WID];              // 2.1 MB  [p][b][o]
__device__ float2 g_G [BATCH*MDIM*MODES*WID];       // 16.8 MB [b][m][ky][o]
__device__ float2 g_W [NLAYERS*512*64*64];          // 67 MB   folded W'=W(I+lin_w)
__device__ float2 g_tw[256];                        // e^{2*pi*i*k/256}

// ---------------- twiddle table ----------------------------------------------
__global__ void k_twiddle() {
    int k = threadIdx.x;
    float a = (float)k / 128.0f;          // 2*pi*k/256 = pi * k/128
    g_tw[k] = make_float2(cospif(a), sinpif(a));
}

// ---------------- fold residual linear into spectral weights ------------------
// W'_p = W_p + W_p @ lin_w  (complex W, real lin_w). block = (l,p): 2048 x 256.
__global__ void k_wfold(const float* __restrict__ fw1,
                        const float* __restrict__ fw2,
                        const float* __restrict__ lin_w) {
    int bi = blockIdx.x;
    int p  = bi & 511;
    int l  = bi >> 9;
    __shared__ float2 Wp[64][64];     // 32 KB
    __shared__ float  lws[32][64];    //  8 KB (j-chunk)
    int tid = threadIdx.x;

    const float* fw = (p < 256) ? fw1 : fw2;
    int pq = p & 255;
    size_t base = ((size_t)l * 64 * 64 * 256 + pq) * 2;
    for (int k = tid; k < 4096; k += 256) {
        int i = k >> 6, o = k & 63;
        size_t s = base + (size_t)(i * 64 + o) * 512;
        Wp[i][o] = make_float2(fw[s], fw[s + 1]);
    }

    int i0 = (tid >> 4) * 4;          // 4 rows
    int o0 = (tid & 15) * 4;          // 4 cols
    float accx[4][4], accy[4][4];
#pragma unroll
    for (int ii = 0; ii < 4; ii++)
#pragma unroll
        for (int oo = 0; oo < 4; oo++) { accx[ii][oo] = 0.f; accy[ii][oo] = 0.f; }

    for (int ch = 0; ch < 2; ch++) {
        __syncthreads();
        for (int k = tid; k < 2048; k += 256)
            lws[k >> 6][k & 63] = lin_w[(size_t)l * 4096 + (ch * 32 + (k >> 6)) * 64 + (k & 63)];
        __syncthreads();
#pragma unroll 8
        for (int jj = 0; jj < 32; jj++) {
            int j = ch * 32 + jj;
            float4 w4 = *(const float4*)&lws[jj][o0];
            float2 a0 = Wp[i0 + 0][j];
            float2 a1 = Wp[i0 + 1][j];
            float2 a2 = Wp[i0 + 2][j];
            float2 a3 = Wp[i0 + 3][j];
            accx[0][0] += a0.x * w4.x; accy[0][0] += a0.y * w4.x;
            accx[0][1] += a0.x * w4.y; accy[0][1] += a0.y * w4.y;
            accx[0][2] += a0.x * w4.z; accy[0][2] += a0.y * w4.z;
            accx[0][3] += a0.x * w4.w; accy[0][3] += a0.y * w4.w;
            accx[1][0] += a1.x * w4.x; accy[1][0] += a1.y * w4.x;
            accx[1][1] += a1.x * w4.y; accy[1][1] += a1.y * w4.y;
            accx[1][2] += a1.x * w4.z; accy[1][2] += a1.y * w4.z;
            accx[1][3] += a1.x * w4.w; accy[1][3] += a1.y * w4.w;
            accx[2][0] += a2.x * w4.x; accy[2][0] += a2.y * w4.x;
            accx[2][1] += a2.x * w4.y; accy[2][1] += a2.y * w4.y;
            accx[2][2] += a2.x * w4.z; accy[2][2] += a2.y * w4.z;
            accx[2][3] += a2.x * w4.w; accy[2][3] += a2.y * w4.w;
            accx[3][0] += a3.x * w4.x; accy[3][0] += a3.y * w4.x;
            accx[3][1] += a3.x * w4.y; accy[3][1] += a3.y * w4.y;
            accx[3][2] += a3.x * w4.z; accy[3][2] += a3.y * w4.z;
            accx[3][3] += a3.x * w4.w; accy[3][3] += a3.y * w4.w;
        }
    }
    float2* wout = g_W + (size_t)bi * 4096;
#pragma unroll
    for (int ii = 0; ii < 4; ii++)
#pragma unroll
        for (int oo = 0; oo < 4; oo++) {
            float2 idv = Wp[i0 + ii][o0 + oo];
            wout[(i0 + ii) * 64 + o0 + oo] =
                make_float2(idv.x + accx[ii][oo], idv.y + accy[ii][oo]);
        }
}

// ---------------- input projection -------------------------------------------
__global__ void k_inproj(const float* __restrict__ x,
                         const float* __restrict__ in_w,
                         const float* __restrict__ in_b) {
    int idx = blockIdx.x * blockDim.x + threadIdx.x;   // over B*M*N*64
    int c   = idx & 63;
    int pix = idx >> 6;
    int n = pix & 255;
    int m = (pix >> 8) & 255;
    const float* xp = x + (size_t)pix * 3;
    float pm = -1.0f + ((float)m + 0.5f) * (2.0f / 256.0f);
    float pn = -1.0f + ((float)n + 0.5f) * (2.0f / 256.0f);
    float acc = in_b[c];
    acc += xp[0] * in_w[0 * WID + c];
    acc += xp[1] * in_w[1 * WID + c];
    acc += xp[2] * in_w[2 * WID + c];
    acc += pm    * in_w[3 * WID + c];
    acc += pn    * in_w[4 * WID + c];
    g_h[idx] = acc;
}

// ---------------- forward DFT along n (h -> T1) -------------------------------
__global__ void k_f1() {
    int bm = blockIdx.x;
    __shared__ float2 tw[256];
    __shared__ float  hs[64][64];
    int tid = threadIdx.x;
    tw[tid] = g_tw[tid];
    int ky = tid >> 4, cg = tid & 15;
    const float4* hp4 = (const float4*)(g_h + (size_t)bm * NDIM * WID);
    float ar[4] = {0.f, 0.f, 0.f, 0.f}, ai[4] = {0.f, 0.f, 0.f, 0.f};
    for (int ch = 0; ch < 4; ch++) {
        int n0 = ch * 64;
        __syncthreads();
#pragma unroll
        for (int i = 0; i < 4; i++) {
            int f = tid + i * 256;
            int row = f >> 4, col4 = f & 15;
            float4 v = hp4[(size_t)(n0 + row) * 16 + col4];
            *(float4*)&hs[row][col4 * 4] = v;
        }
        __syncthreads();
#pragma unroll 8
        for (int nn = 0; nn < 64; nn++) {
            int n = n0 + nn;
            float2 t = tw[(ky * n) & 255];
            float4 hv = *(const float4*)&hs[nn][cg * 4];
            ar[0] += hv.x * t.x; ai[0] -= hv.x * t.y;
            ar[1] += hv.y * t.x; ai[1] -= hv.y * t.y;
            ar[2] += hv.z * t.x; ai[2] -= hv.z * t.y;
            ar[3] += hv.w * t.x; ai[3] -= hv.w * t.y;
        }
    }
    float4* op = (float4*)(g_t1 + (size_t)bm * MODES * WID + ky * 64 + cg * 4);
    op[0] = make_float4(ar[0], ai[0], ar[1], ai[1]);
    op[1] = make_float4(ar[2], ai[2], ar[3], ai[3]);
}

// ---------------- forward DFT along m (T1 -> X) -------------------------------
__global__ void k_f2() {
    int bi = blockIdx.x;
    int cchunk = bi & 7;
    int ky     = (bi >> 3) & 15;
    int b      = bi >> 7;
    __shared__ float2 tw[256];
    __shared__ float2 ts[64][8];
    int tid = threadIdx.x;
    tw[tid] = g_tw[tid];
    int j = tid >> 3, cl = tid & 7;
    int c0 = cchunk * 8;
    int kx = (j < 16) ? j : (224 + j);
    float ar = 0.f, ai = 0.f;
    for (int ch = 0; ch < 4; ch++) {
        int m0 = ch * 64;
        __syncthreads();
#pragma unroll
        for (int i = 0; i < 2; i++) {
            int k = tid + i * 256;
            int m = k >> 3, cc = k & 7;
            ts[m][cc] = g_t1[((size_t)((b * 256 + m0 + m) * 16 + ky)) * 64 + c0 + cc];
        }
        __syncthreads();
#pragma unroll 8
        for (int mm = 0; mm < 64; mm++) {
            int m = m0 + mm;
            float2 w = tw[(kx * m) & 255];
            float2 t = ts[mm][cl];
            ar += t.x * w.x + t.y * w.y;
            ai += t.y * w.x - t.x * w.y;
        }
    }
    int p = (j < 16) ? (j * 16 + ky) : (256 + (j - 16) * 16 + ky);
    g_X[((size_t)p * 8 + b) * WID + c0 + cl] = make_float2(ar, ai);
}

// ---------------- spectral mixing (X -> Y) with folded weights ----------------
__global__ void k_mix(int layer) {
    int p = blockIdx.x;
    __shared__ float2 W [64][64];
    __shared__ float2 Xs[8][64];
    int tid = threadIdx.x;
    const float2* wp = g_W + ((size_t)layer * 512 + p) * 4096;
    for (int k = tid; k < 4096; k += 256)
        W[k >> 6][k & 63] = wp[k];
    for (int k = tid; k < 512; k += 256)
        Xs[k >> 6][k & 63] = g_X[(size_t)p * 512 + k];
    __syncthreads();
#pragma unroll
    for (int rep = 0; rep < 2; rep++) {
        int idx = tid + rep * 256;
        int b = idx >> 6, o = idx & 63;
        float accr = 0.f, acci = 0.f;
#pragma unroll
        for (int i = 0; i < 64; i++) {
            float2 xv = Xs[b][i];
            float2 wv = W[i][o];
            accr += xv.x * wv.x - xv.y * wv.y;
            acci += xv.x * wv.y + xv.y * wv.x;
        }
        g_Y[(size_t)p * 512 + idx] = make_float2(accr, acci);
    }
}

// ---------------- inverse DFT along kx (Y -> G) -------------------------------
__global__ void k_i1() {
    int bi = blockIdx.x;
    int quad = bi & 3;
    int ky   = (bi >> 2) & 15;
    int b    = bi >> 6;
    __shared__ float2 tw[256];
    __shared__ float2 Ys[32][64];
    int tid = threadIdx.x;
    tw[tid] = g_tw[tid];
    for (int k = tid; k < 2048; k += 256) {
        int j = k >> 6, o = k & 63;
        int half = j >> 4, jl = j & 15;
        int p = half * 256 + jl * 16 + ky;
        Ys[j][o] = g_Y[((size_t)p * 8 + b) * 64 + o];
    }
    __syncthreads();
    int o = tid & 63, msub = tid >> 6;
    for (int it = 0; it < 16; it++) {
        int m = quad * 64 + it * 4 + msub;
        float sr = 0.f, si = 0.f;
#pragma unroll
        for (int j = 0; j < 32; j++) {
            int kx = (j < 16) ? j : (224 + j);
            float2 w = tw[(kx * m) & 255];
            float2 v = Ys[j][o];
            sr += v.x * w.x - v.y * w.y;
            si += v.x * w.y + v.y * w.x;
        }
        g_G[(((size_t)b * 256 + m) * 16 + ky) * 64 + o] = make_float2(sr, si);
    }
}

// ---------------- i2: inverse DFT along n + bias + ReLU (GEMM folded out) -----
// block = (b,m): 2048 x 256. n-parity pairing: y[n]=E+O, y[n+128]=E-O.
__global__ void k_i2(const float* __restrict__ lin_b, int layer) {
    int bm = blockIdx.x;
    __shared__ float2 tw[256];
    __shared__ float2 Gs[16][64];   // prescaled
    __shared__ float  lb[64];
    int tid = threadIdx.x;
    tw[tid] = g_tw[tid];
    for (int k = tid; k < 1024; k += 256) {
        int ky = k >> 6, o = k & 63;
        float s = (ky == 0 ? 1.0f : 2.0f) * (1.0f / 65536.0f);
        float2 v = g_G[(size_t)bm * 1024 + k];
        Gs[ky][o] = make_float2(v.x * s, v.y * s);
    }
    if (tid < 64) lb[tid] = lin_b[layer * 64 + tid];
    __syncthreads();
    int tx = tid & 15, ty = tid >> 4;
    int c0 = tx * 4;
    float lb0 = lb[c0], lb1 = lb[c0 + 1], lb2 = lb[c0 + 2], lb3 = lb[c0 + 3];
    float* hout = g_h + (size_t)bm * NDIM * WID;
#pragma unroll
    for (int k = 0; k < 8; k++) {
        int n = ty * 8 + k;                  // 0..127
        float E0 = 0.f, E1 = 0.f, E2 = 0.f, E3 = 0.f;
        float O0 = 0.f, O1 = 0.f, O2 = 0.f, O3 = 0.f;
#pragma unroll
        for (int ky = 0; ky < 16; ky += 2) {
            float2 te = tw[(ky * n) & 255];
            float4 ae = *(const float4*)&Gs[ky][c0];
            float4 be = *(const float4*)&Gs[ky][c0 + 2];
            E0 += ae.x * te.x - ae.y * te.y;
            E1 += ae.z * te.x - ae.w * te.y;
            E2 += be.x * te.x - be.y * te.y;
            E3 += be.z * te.x - be.w * te.y;
            float2 to = tw[((ky + 1) * n) & 255];
            float4 ao = *(const float4*)&Gs[ky + 1][c0];
            float4 bo = *(const float4*)&Gs[ky + 1][c0 + 2];
            O0 += ao.x * to.x - ao.y * to.y;
            O1 += ao.z * to.x - ao.w * to.y;
            O2 += bo.x * to.x - bo.y * to.y;
            O3 += bo.z * to.x - bo.w * to.y;
        }
        float4 r0, r1;
        r0.x = fmaxf(E0 + O0 + lb0, 0.f);
        r0.y = fmaxf(E1 + O1 + lb1, 0.f);
        r0.z = fmaxf(E2 + O2 + lb2, 0.f);
        r0.w = fmaxf(E3 + O3 + lb3, 0.f);
        r1.x = fmaxf(E0 - O0 + lb0, 0.f);
        r1.y = fmaxf(E1 - O1 + lb1, 0.f);
        r1.z = fmaxf(E2 - O2 + lb2, 0.f);
        r1.w = fmaxf(E3 - O3 + lb3, 0.f);
        *(float4*)&hout[(size_t)n * WID + c0] = r0;
        *(float4*)&hout[(size_t)(n + 128) * WID + c0] = r1;
    }
}

// ---------------- output head: relu(h@W1+b1)@W2+b2 ----------------------------
__global__ void k_out(const float* __restrict__ out1_w,
                      const float* __restrict__ out1_b,
                      const float* __restrict__ out2_w,
                      const float* __restrict__ out2_b,
                      float* __restrict__ out) {
    int bm = blockIdx.x;
    __shared__ float hs [32][65];
    __shared__ float w1s[64][128];
    __shared__ float b1s[128];
    __shared__ float w2s[128];
    int tid = threadIdx.x;
    for (int k = tid; k < 8192; k += 256) w1s[k >> 7][k & 127] = out1_w[k];
    if (tid < 128) { b1s[tid] = out1_b[tid]; w2s[tid] = out2_w[tid]; }
    float b2 = out2_b[0];
    const float* hp = g_h + (size_t)bm * NDIM * WID;
    float* op = out + (size_t)bm * NDIM;
    int tx = tid & 31, ty = tid >> 5;
    for (int rnd = 0; rnd < 8; rnd++) {
        __syncthreads();
        for (int k = tid; k < 2048; k += 256)
            hs[k >> 6][k & 63] = hp[(size_t)rnd * 2048 + k];
        __syncthreads();
        float acc[4][4];
#pragma unroll
        for (int k = 0; k < 4; k++)
#pragma unroll
            for (int q = 0; q < 4; q++) acc[k][q] = b1s[tx * 4 + q];
#pragma unroll
        for (int j = 0; j < 64; j++) {
            float4 w4 = *(const float4*)&w1s[j][tx * 4];
#pragma unroll
            for (int k = 0; k < 4; k++) {
                float hv = hs[ty * 4 + k][j];
                acc[k][0] += hv * w4.x;
                acc[k][1] += hv * w4.y;
                acc[k][2] += hv * w4.z;
                acc[k][3] += hv * w4.w;
            }
        }
#pragma unroll
        for (int k = 0; k < 4; k++) {
            float part = fmaxf(acc[k][0], 0.f) * w2s[tx * 4 + 0]
                       + fmaxf(acc[k][1], 0.f) * w2s[tx * 4 + 1]
                       + fmaxf(acc[k][2], 0.f) * w2s[tx * 4 + 2]
                       + fmaxf(acc[k][3], 0.f) * w2s[tx * 4 + 3];
#pragma unroll
            for (int off = 16; off > 0; off >>= 1)
                part += __shfl_xor_sync(0xffffffffu, part, off);
            if (tx == 0) op[rnd * 32 + ty * 4 + k] = part + b2;
        }
    }
}

// ---------------- launch ------------------------------------------------------
extern "C" void kernel_launch(void* const* d_in, const int* in_sizes, int n_in,
                              void* d_out, int out_size) {
    const float* x      = (const float*)d_in[0];
    const float* in_w   = (const float*)d_in[1];
    const float* in_b   = (const float*)d_in[2];
    const float* fw1    = (const float*)d_in[3];
    const float* fw2    = (const float*)d_in[4];
    const float* lin_w  = (const float*)d_in[5];
    const float* lin_b  = (const float*)d_in[6];
    const float* out1_w = (const float*)d_in[7];
    const float* out1_b = (const float*)d_in[8];
    const float* out2_w = (const float*)d_in[9];
    const float* out2_b = (const float*)d_in[10];
    float* out = (float*)d_out;

    k_twiddle<<<1, 256>>>();
    k_wfold<<<NLAYERS * 512, 256>>>(fw1, fw2, lin_w);
    k_inproj<<<(BATCH * MDIM * NDIM * WID) / 256, 256>>>(x, in_w, in_b);
    for (int l = 0; l < NLAYERS; l++) {
        k_f1 <<<BATCH * MDIM, 256>>>();
        k_f2 <<<BATCH * MODES * 8, 256>>>();
        k_mix<<<512, 256>>>(l);
        k_i1 <<<BATCH * MODES * 4, 256>>>();
        k_i2 <<<BATCH * MDIM, 256>>>(lin_b, l);
    }
    k_out<<<BATCH * MDIM, 256>>>(out1_w, out1_b, out2_w, out2_b, out);
}

// round 11
// speedup vs baseline: 2.0135x; 1.1688x over previous
#include <cuda_runtime.h>

#define BATCH 8
#define MDIM 256
#define NDIM 256
#define WID 64
#define MODES 16
#define NLAYERS 4

// ---------------- scratch (static device arrays; no allocations) -------------
__device__ float  g_h [BATCH*MDIM*NDIM*WID];        // 134 MB  [b][m][n][c]
__device__ float2 g_t1[BATCH*MDIM*MODES*WID];       // 16.8 MB [b][m][ky][c]
__device__ float2 g_X [512*BATCH*WID];              // 2.1 MB  [p][b][c]
__device__ float2 g_Y [512*BATCH*WID];              // 2.1 MB  [p][b][o]
__device__ float2 g_G [BATCH*MDIM*MODES*WID];       // 16.8 MB [b][m][ky][o]
__device__ float2 g_W [NLAYERS*512*64*64];          // 67 MB   folded W'=W(I+lin_w)
__device__ float2 g_tw[256];                        // e^{2*pi*i*k/256}

// ---------------- twiddle table ----------------------------------------------
__global__ void k_twiddle() {
    int k = threadIdx.x;
    float a = (float)k / 128.0f;          // 2*pi*k/256 = pi * k/128
    g_tw[k] = make_float2(cospif(a), sinpif(a));
}

// ---------------- fold residual linear into spectral weights ------------------
// W'_p = W_p + W_p @ lin_w  (complex W, real lin_w). block = (l,p): 2048 x 256.
__global__ void k_wfold(const float* __restrict__ fw1,
                        const float* __restrict__ fw2,
                        const float* __restrict__ lin_w) {
    int bi = blockIdx.x;
    int p  = bi & 511;
    int l  = bi >> 9;
    __shared__ float2 Wp[64][64];     // 32 KB
    __shared__ float  lws[32][64];    //  8 KB (j-chunk)
    int tid = threadIdx.x;

    const float* fw = (p < 256) ? fw1 : fw2;
    int pq = p & 255;
    size_t base = ((size_t)l * 64 * 64 * 256 + pq) * 2;
    for (int k = tid; k < 4096; k += 256) {
        int i = k >> 6, o = k & 63;
        size_t s = base + (size_t)(i * 64 + o) * 512;
        Wp[i][o] = make_float2(fw[s], fw[s + 1]);
    }

    int i0 = (tid >> 4) * 4;          // 4 rows
    int o0 = (tid & 15) * 4;          // 4 cols
    float accx[4][4], accy[4][4];
#pragma unroll
    for (int ii = 0; ii < 4; ii++)
#pragma unroll
        for (int oo = 0; oo < 4; oo++) { accx[ii][oo] = 0.f; accy[ii][oo] = 0.f; }

    for (int ch = 0; ch < 2; ch++) {
        __syncthreads();
        for (int k = tid; k < 2048; k += 256)
            lws[k >> 6][k & 63] = lin_w[(size_t)l * 4096 + (ch * 32 + (k >> 6)) * 64 + (k & 63)];
        __syncthreads();
#pragma unroll 8
        for (int jj = 0; jj < 32; jj++) {
            int j = ch * 32 + jj;
            float4 w4 = *(const float4*)&lws[jj][o0];
            float2 a0 = Wp[i0 + 0][j];
            float2 a1 = Wp[i0 + 1][j];
            float2 a2 = Wp[i0 + 2][j];
            float2 a3 = Wp[i0 + 3][j];
            accx[0][0] += a0.x * w4.x; accy[0][0] += a0.y * w4.x;
            accx[0][1] += a0.x * w4.y; accy[0][1] += a0.y * w4.y;
            accx[0][2] += a0.x * w4.z; accy[0][2] += a0.y * w4.z;
            accx[0][3] += a0.x * w4.w; accy[0][3] += a0.y * w4.w;
            accx[1][0] += a1.x * w4.x; accy[1][0] += a1.y * w4.x;
            accx[1][1] += a1.x * w4.y; accy[1][1] += a1.y * w4.y;
            accx[1][2] += a1.x * w4.z; accy[1][2] += a1.y * w4.z;
            accx[1][3] += a1.x * w4.w; accy[1][3] += a1.y * w4.w;
            accx[2][0] += a2.x * w4.x; accy[2][0] += a2.y * w4.x;
            accx[2][1] += a2.x * w4.y; accy[2][1] += a2.y * w4.y;
            accx[2][2] += a2.x * w4.z; accy[2][2] += a2.y * w4.z;
            accx[2][3] += a2.x * w4.w; accy[2][3] += a2.y * w4.w;
            accx[3][0] += a3.x * w4.x; accy[3][0] += a3.y * w4.x;
            accx[3][1] += a3.x * w4.y; accy[3][1] += a3.y * w4.y;
            accx[3][2] += a3.x * w4.z; accy[3][2] += a3.y * w4.z;
            accx[3][3] += a3.x * w4.w; accy[3][3] += a3.y * w4.w;
        }
    }
    float2* wout = g_W + (size_t)bi * 4096;
#pragma unroll
    for (int ii = 0; ii < 4; ii++)
#pragma unroll
        for (int oo = 0; oo < 4; oo++) {
            float2 idv = Wp[i0 + ii][o0 + oo];
            wout[(i0 + ii) * 64 + o0 + oo] =
                make_float2(idv.x + accx[ii][oo], idv.y + accy[ii][oo]);
        }
}

// ---------------- input projection -------------------------------------------
__global__ void k_inproj(const float* __restrict__ x,
                         const float* __restrict__ in_w,
                         const float* __restrict__ in_b) {
    int idx = blockIdx.x * blockDim.x + threadIdx.x;   // over B*M*N*64
    int c   = idx & 63;
    int pix = idx >> 6;
    int n = pix & 255;
    int m = (pix >> 8) & 255;
    const float* xp = x + (size_t)pix * 3;
    float pm = -1.0f + ((float)m + 0.5f) * (2.0f / 256.0f);
    float pn = -1.0f + ((float)n + 0.5f) * (2.0f / 256.0f);
    float acc = in_b[c];
    acc += xp[0] * in_w[0 * WID + c];
    acc += xp[1] * in_w[1 * WID + c];
    acc += xp[2] * in_w[2 * WID + c];
    acc += pm    * in_w[3 * WID + c];
    acc += pn    * in_w[4 * WID + c];
    g_h[idx] = acc;
}

// ---------------- forward DFT along n (h -> T1)  [radix-2 parity] -------------
// block = (b,m): 2048 x 256. thread = (ky, cg). E/O staged during copy;
// even ky reads Es only, odd ky reads Os only. Halves LDS + FMA.
__global__ void k_f1() {
    int bm = blockIdx.x;
    __shared__ float2 tw[256];
    __shared__ float  Es[64][64];          // 16 KB
    __shared__ float  Os[64][64];          // 16 KB
    int tid = threadIdx.x;
    tw[tid] = g_tw[tid];
    int ky = tid >> 4, cg = tid & 15;
    const float(*src)[64] = (ky & 1) ? Os : Es;
    const float4* hp4 = (const float4*)(g_h + (size_t)bm * NDIM * WID);
    float ar[4] = {0.f, 0.f, 0.f, 0.f}, ai[4] = {0.f, 0.f, 0.f, 0.f};
    for (int ch = 0; ch < 2; ch++) {
        int n0 = ch * 64;
        __syncthreads();
#pragma unroll
        for (int i = 0; i < 4; i++) {
            int f = tid + i * 256;                 // 1024 pair-slots
            int row = f >> 4, col4 = f & 15;
            float4 v0 = hp4[(size_t)(n0 + row) * 16 + col4];
            float4 v1 = hp4[(size_t)(n0 + 128 + row) * 16 + col4];
            float4 e, o;
            e.x = v0.x + v1.x; e.y = v0.y + v1.y;
            e.z = v0.z + v1.z; e.w = v0.w + v1.w;
            o.x = v0.x - v1.x; o.y = v0.y - v1.y;
            o.z = v0.z - v1.z; o.w = v0.w - v1.w;
            *(float4*)&Es[row][col4 * 4] = e;
            *(float4*)&Os[row][col4 * 4] = o;
        }
        __syncthreads();
#pragma unroll 8
        for (int nn = 0; nn < 64; nn++) {
            int n = n0 + nn;                       // 0..127
            float2 t = tw[(ky * n) & 255];
            float4 hv = *(const float4*)&src[nn][cg * 4];
            ar[0] += hv.x * t.x; ai[0] -= hv.x * t.y;
            ar[1] += hv.y * t.x; ai[1] -= hv.y * t.y;
            ar[2] += hv.z * t.x; ai[2] -= hv.z * t.y;
            ar[3] += hv.w * t.x; ai[3] -= hv.w * t.y;
        }
    }
    float4* op = (float4*)(g_t1 + (size_t)bm * MODES * WID + ky * 64 + cg * 4);
    op[0] = make_float4(ar[0], ai[0], ar[1], ai[1]);
    op[1] = make_float4(ar[2], ai[2], ar[3], ai[3]);
}

// ---------------- forward DFT along m (T1 -> X)  [radix-2 parity] -------------
// block = (b, ky, cchunk): 1024 x 256. kx parity == j parity (224 even).
__global__ void k_f2() {
    int bi = blockIdx.x;
    int cchunk = bi & 7;
    int ky     = (bi >> 3) & 15;
    int b      = bi >> 7;
    __shared__ float2 tw[256];
    __shared__ float2 Es[64][8];           // 4 KB
    __shared__ float2 Os[64][8];           // 4 KB
    int tid = threadIdx.x;
    tw[tid] = g_tw[tid];
    int j = tid >> 3, cl = tid & 7;
    int c0 = cchunk * 8;
    int kx = (j < 16) ? j : (224 + j);
    const float2(*src)[8] = (j & 1) ? Os : Es;
    float ar = 0.f, ai = 0.f;
    for (int ch = 0; ch < 2; ch++) {
        int m0 = ch * 64;
        __syncthreads();
#pragma unroll
        for (int i = 0; i < 2; i++) {
            int k = tid + i * 256;                 // 512 pair-slots
            int m = k >> 3, cc = k & 7;
            float2 a = g_t1[((size_t)((b * 256 + m0 + m) * 16 + ky)) * 64 + c0 + cc];
            float2 d = g_t1[((size_t)((b * 256 + m0 + 128 + m) * 16 + ky)) * 64 + c0 + cc];
            Es[m][cc] = make_float2(a.x + d.x, a.y + d.y);
            Os[m][cc] = make_float2(a.x - d.x, a.y - d.y);
        }
        __syncthreads();
#pragma unroll 8
        for (int mm = 0; mm < 64; mm++) {
            int m = m0 + mm;                       // 0..127
            float2 w = tw[(kx * m) & 255];
            float2 t = src[mm][cl];
            ar += t.x * w.x + t.y * w.y;           // T1 * conj(w)
            ai += t.y * w.x - t.x * w.y;
        }
    }
    int p = (j < 16) ? (j * 16 + ky) : (256 + (j - 16) * 16 + ky);
    g_X[((size_t)p * 8 + b) * WID + c0 + cl] = make_float2(ar, ai);
}

// ---------------- spectral mixing (X -> Y) with folded weights ----------------
__global__ void k_mix(int layer) {
    int p = blockIdx.x;
    __shared__ float2 W [64][64];
    __shared__ float2 Xs[8][64];
    int tid = threadIdx.x;
    const float2* wp = g_W + ((size_t)layer * 512 + p) * 4096;
    for (int k = tid; k < 4096; k += 256)
        W[k >> 6][k & 63] = wp[k];
    for (int k = tid; k < 512; k += 256)
        Xs[k >> 6][k & 63] = g_X[(size_t)p * 512 + k];
    __syncthreads();
#pragma unroll
    for (int rep = 0; rep < 2; rep++) {
        int idx = tid + rep * 256;
        int b = idx >> 6, o = idx & 63;
        float accr = 0.f, acci = 0.f;
#pragma unroll
        for (int i = 0; i < 64; i++) {
            float2 xv = Xs[b][i];
            float2 wv = W[i][o];
            accr += xv.x * wv.x - xv.y * wv.y;
            acci += xv.x * wv.y + xv.y * wv.x;
        }
        g_Y[(size_t)p * 512 + idx] = make_float2(accr, acci);
    }
}

// ---------------- inverse DFT along kx (Y -> G)  [radix-2 output pairing] -----
// block = (b, ky, quad): 512 x 256. quad covers m' in [quad*32, quad*32+32);
// outputs m' and m'+128 from E (even kx) / O (odd kx) partial sums.
__global__ void k_i1() {
    int bi = blockIdx.x;
    int quad = bi & 3;
    int ky   = (bi >> 2) & 15;
    int b    = bi >> 6;
    __shared__ float2 tw[256];
    __shared__ float2 Ys[32][64];
    int tid = threadIdx.x;
    tw[tid] = g_tw[tid];
    for (int k = tid; k < 2048; k += 256) {
        int j = k >> 6, o = k & 63;
        int half = j >> 4, jl = j & 15;
        int p = half * 256 + jl * 16 + ky;
        Ys[j][o] = g_Y[((size_t)p * 8 + b) * 64 + o];
    }
    __syncthreads();
    int o = tid & 63, msub = tid >> 6;
    for (int it = 0; it < 8; it++) {
        int m = quad * 32 + it * 4 + msub;         // 0..127
        float Er = 0.f, Ei = 0.f, Or = 0.f, Oi = 0.f;
#pragma unroll
        for (int j = 0; j < 32; j += 2) {
            int kxe = (j < 16) ? j : (224 + j);    // even kx
            float2 we = tw[(kxe * m) & 255];
            float2 ve = Ys[j][o];
            Er += ve.x * we.x - ve.y * we.y;
            Ei += ve.x * we.y + ve.y * we.x;
            int kxo = (j + 1 < 16) ? (j + 1) : (225 + j);  // odd kx
            float2 wo = tw[(kxo * m) & 255];
            float2 vo = Ys[j + 1][o];
            Or += vo.x * wo.x - vo.y * wo.y;
            Oi += vo.x * wo.y + vo.y * wo.x;
        }
        g_G[(((size_t)b * 256 + m) * 16 + ky) * 64 + o] =
            make_float2(Er + Or, Ei + Oi);
        g_G[(((size_t)b * 256 + m + 128) * 16 + ky) * 64 + o] =
            make_float2(Er - Or, Ei - Oi);
    }
}

// ---------------- i2: inverse DFT along n + bias + ReLU (GEMM folded out) -----
// block = (b,m): 2048 x 256. n-parity pairing: y[n]=E+O, y[n+128]=E-O.
__global__ void k_i2(const float* __restrict__ lin_b, int layer) {
    int bm = blockIdx.x;
    __shared__ float2 tw[256];
    __shared__ float2 Gs[16][64];   // prescaled
    __shared__ float  lb[64];
    int tid = threadIdx.x;
    tw[tid] = g_tw[tid];
    for (int k = tid; k < 1024; k += 256) {
        int ky = k >> 6, o = k & 63;
        float s = (ky == 0 ? 1.0f : 2.0f) * (1.0f / 65536.0f);
        float2 v = g_G[(size_t)bm * 1024 + k];
        Gs[ky][o] = make_float2(v.x * s, v.y * s);
    }
    if (tid < 64) lb[tid] = lin_b[layer * 64 + tid];
    __syncthreads();
    int tx = tid & 15, ty = tid >> 4;
    int c0 = tx * 4;
    float lb0 = lb[c0], lb1 = lb[c0 + 1], lb2 = lb[c0 + 2], lb3 = lb[c0 + 3];
    float* hout = g_h + (size_t)bm * NDIM * WID;
#pragma unroll
    for (int k = 0; k < 8; k++) {
        int n = ty * 8 + k;                  // 0..127
        float E0 = 0.f, E1 = 0.f, E2 = 0.f, E3 = 0.f;
        float O0 = 0.f, O1 = 0.f, O2 = 0.f, O3 = 0.f;
#pragma unroll
        for (int ky = 0; ky < 16; ky += 2) {
            float2 te = tw[(ky * n) & 255];
            float4 ae = *(const float4*)&Gs[ky][c0];
            float4 be = *(const float4*)&Gs[ky][c0 + 2];
            E0 += ae.x * te.x - ae.y * te.y;
            E1 += ae.z * te.x - ae.w * te.y;
            E2 += be.x * te.x - be.y * te.y;
            E3 += be.z * te.x - be.w * te.y;
            float2 to = tw[((ky + 1) * n) & 255];
            float4 ao = *(const float4*)&Gs[ky + 1][c0];
            float4 bo = *(const float4*)&Gs[ky + 1][c0 + 2];
            O0 += ao.x * to.x - ao.y * to.y;
            O1 += ao.z * to.x - ao.w * to.y;
            O2 += bo.x * to.x - bo.y * to.y;
            O3 += bo.z * to.x - bo.w * to.y;
        }
        float4 r0, r1;
        r0.x = fmaxf(E0 + O0 + lb0, 0.f);
        r0.y = fmaxf(E1 + O1 + lb1, 0.f);
        r0.z = fmaxf(E2 + O2 + lb2, 0.f);
        r0.w = fmaxf(E3 + O3 + lb3, 0.f);
        r1.x = fmaxf(E0 - O0 + lb0, 0.f);
        r1.y = fmaxf(E1 - O1 + lb1, 0.f);
        r1.z = fmaxf(E2 - O2 + lb2, 0.f);
        r1.w = fmaxf(E3 - O3 + lb3, 0.f);
        *(float4*)&hout[(size_t)n * WID + c0] = r0;
        *(float4*)&hout[(size_t)(n + 128) * WID + c0] = r1;
    }
}

// ---------------- output head: relu(h@W1+b1)@W2+b2 ----------------------------
__global__ void k_out(const float* __restrict__ out1_w,
                      const float* __restrict__ out1_b,
                      const float* __restrict__ out2_w,
                      const float* __restrict__ out2_b,
                      float* __restrict__ out) {
    int bm = blockIdx.x;
    __shared__ float hs [32][65];
    __shared__ float w1s[64][128];
    __shared__ float b1s[128];
    __shared__ float w2s[128];
    int tid = threadIdx.x;
    for (int k = tid; k < 8192; k += 256) w1s[k >> 7][k & 127] = out1_w[k];
    if (tid < 128) { b1s[tid] = out1_b[tid]; w2s[tid] = out2_w[tid]; }
    float b2 = out2_b[0];
    const float* hp = g_h + (size_t)bm * NDIM * WID;
    float* op = out + (size_t)bm * NDIM;
    int tx = tid & 31, ty = tid >> 5;
    for (int rnd = 0; rnd < 8; rnd++) {
        __syncthreads();
        for (int k = tid; k < 2048; k += 256)
            hs[k >> 6][k & 63] = hp[(size_t)rnd * 2048 + k];
        __syncthreads();
        float acc[4][4];
#pragma unroll
        for (int k = 0; k < 4; k++)
#pragma unroll
            for (int q = 0; q < 4; q++) acc[k][q] = b1s[tx * 4 + q];
#pragma unroll
        for (int j = 0; j < 64; j++) {
            float4 w4 = *(const float4*)&w1s[j][tx * 4];
#pragma unroll
            for (int k = 0; k < 4; k++) {
                float hv = hs[ty * 4 + k][j];
                acc[k][0] += hv * w4.x;
                acc[k][1] += hv * w4.y;
                acc[k][2] += hv * w4.z;
                acc[k][3] += hv * w4.w;
            }
        }
#pragma unroll
        for (int k = 0; k < 4; k++) {
            float part = fmaxf(acc[k][0], 0.f) * w2s[tx * 4 + 0]
                       + fmaxf(acc[k][1], 0.f) * w2s[tx * 4 + 1]
                       + fmaxf(acc[k][2], 0.f) * w2s[tx * 4 + 2]
                       + fmaxf(acc[k][3], 0.f) * w2s[tx * 4 + 3];
#pragma unroll
            for (int off = 16; off > 0; off >>= 1)
                part += __shfl_xor_sync(0xffffffffu, part, off);
            if (tx == 0) op[rnd * 32 + ty * 4 + k] = part + b2;
        }
    }
}

// ---------------- launch ------------------------------------------------------
extern "C" void kernel_launch(void* const* d_in, const int* in_sizes, int n_in,
                              void* d_out, int out_size) {
    const float* x      = (const float*)d_in[0];
    const float* in_w   = (const float*)d_in[1];
    const float* in_b   = (const float*)d_in[2];
    const float* fw1    = (const float*)d_in[3];
    const float* fw2    = (const float*)d_in[4];
    const float* lin_w  = (const float*)d_in[5];
    const float* lin_b  = (const float*)d_in[6];
    const float* out1_w = (const float*)d_in[7];
    const float* out1_b = (const float*)d_in[8];
    const float* out2_w = (const float*)d_in[9];
    const float* out2_b = (const float*)d_in[10];
    float* out = (float*)d_out;

    k_twiddle<<<1, 256>>>();
    k_wfold<<<NLAYERS * 512, 256>>>(fw1, fw2, lin_w);
    k_inproj<<<(BATCH * MDIM * NDIM * WID) / 256, 256>>>(x, in_w, in_b);
    for (int l = 0; l < NLAYERS; l++) {
        k_f1 <<<BATCH * MDIM, 256>>>();
        k_f2 <<<BATCH * MODES * 8, 256>>>();
        k_mix<<<512, 256>>>(l);
        k_i1 <<<BATCH * MODES * 4, 256>>>();
        k_i2 <<<BATCH * MDIM, 256>>>(lin_b, l);
    }
    k_out<<<BATCH * MDIM, 256>>>(out1_w, out1_b, out2_w, out2_b, out);
}

// round 12
// speedup vs baseline: 2.1218x; 1.0538x over previous
#include <cuda_runtime.h>

#define BATCH 8
#define MDIM 256
#define NDIM 256
#define WID 64
#define MODES 16
#define NLAYERS 4

// ---------------- scratch (static device arrays; no allocations) -------------
__device__ float  g_h [BATCH*MDIM*NDIM*WID];        // 134 MB  [b][m][n][c]
__device__ float2 g_t1[BATCH*MDIM*MODES*WID];       // 16.8 MB [b][m][ky][c]
__device__ float2 g_X [512*BATCH*WID];              // 2.1 MB  [p][b][c]
__device__ float2 g_Y [512*BATCH*WID];              // 2.1 MB  [p][b][o]
__device__ float2 g_G [BATCH*MDIM*MODES*WID];       // 16.8 MB [b][m][ky][o]
__device__ float2 g_W [NLAYERS*512*64*64];          // 67 MB   folded W'=W(I+lin_w)
__device__ float2 g_tw[256];                        // e^{2*pi*i*k/256}

// complex mul: t * w  (+ angle)
__device__ __forceinline__ float2 cmul(float2 t, float2 w) {
    return make_float2(t.x * w.x - t.y * w.y, t.x * w.y + t.y * w.x);
}

// ---------------- twiddle table ----------------------------------------------
__global__ void k_twiddle() {
    int k = threadIdx.x;
    float a = (float)k / 128.0f;          // 2*pi*k/256 = pi * k/128
    g_tw[k] = make_float2(cospif(a), sinpif(a));
}

// ---------------- fold residual linear into spectral weights ------------------
__global__ void k_wfold(const float* __restrict__ fw1,
                        const float* __restrict__ fw2,
                        const float* __restrict__ lin_w) {
    int bi = blockIdx.x;
    int p  = bi & 511;
    int l  = bi >> 9;
    __shared__ float2 Wp[64][64];     // 32 KB
    __shared__ float  lws[32][64];    //  8 KB
    int tid = threadIdx.x;

    const float* fw = (p < 256) ? fw1 : fw2;
    int pq = p & 255;
    size_t base = ((size_t)l * 64 * 64 * 256 + pq) * 2;
    for (int k = tid; k < 4096; k += 256) {
        int i = k >> 6, o = k & 63;
        size_t s = base + (size_t)(i * 64 + o) * 512;
        Wp[i][o] = make_float2(fw[s], fw[s + 1]);
    }

    int i0 = (tid >> 4) * 4;
    int o0 = (tid & 15) * 4;
    float accx[4][4], accy[4][4];
#pragma unroll
    for (int ii = 0; ii < 4; ii++)
#pragma unroll
        for (int oo = 0; oo < 4; oo++) { accx[ii][oo] = 0.f; accy[ii][oo] = 0.f; }

    for (int ch = 0; ch < 2; ch++) {
        __syncthreads();
        for (int k = tid; k < 2048; k += 256)
            lws[k >> 6][k & 63] = lin_w[(size_t)l * 4096 + (ch * 32 + (k >> 6)) * 64 + (k & 63)];
        __syncthreads();
#pragma unroll 8
        for (int jj = 0; jj < 32; jj++) {
            int j = ch * 32 + jj;
            float4 w4 = *(const float4*)&lws[jj][o0];
            float2 a0 = Wp[i0 + 0][j];
            float2 a1 = Wp[i0 + 1][j];
            float2 a2 = Wp[i0 + 2][j];
            float2 a3 = Wp[i0 + 3][j];
            accx[0][0] += a0.x * w4.x; accy[0][0] += a0.y * w4.x;
            accx[0][1] += a0.x * w4.y; accy[0][1] += a0.y * w4.y;
            accx[0][2] += a0.x * w4.z; accy[0][2] += a0.y * w4.z;
            accx[0][3] += a0.x * w4.w; accy[0][3] += a0.y * w4.w;
            accx[1][0] += a1.x * w4.x; accy[1][0] += a1.y * w4.x;
            accx[1][1] += a1.x * w4.y; accy[1][1] += a1.y * w4.y;
            accx[1][2] += a1.x * w4.z; accy[1][2] += a1.y * w4.z;
            accx[1][3] += a1.x * w4.w; accy[1][3] += a1.y * w4.w;
            accx[2][0] += a2.x * w4.x; accy[2][0] += a2.y * w4.x;
            accx[2][1] += a2.x * w4.y; accy[2][1] += a2.y * w4.y;
            accx[2][2] += a2.x * w4.z; accy[2][2] += a2.y * w4.z;
            accx[2][3] += a2.x * w4.w; accy[2][3] += a2.y * w4.w;
            accx[3][0] += a3.x * w4.x; accy[3][0] += a3.y * w4.x;
            accx[3][1] += a3.x * w4.y; accy[3][1] += a3.y * w4.y;
            accx[3][2] += a3.x * w4.z; accy[3][2] += a3.y * w4.z;
            accx[3][3] += a3.x * w4.w; accy[3][3] += a3.y * w4.w;
        }
    }
    float2* wout = g_W + (size_t)bi * 4096;
#pragma unroll
    for (int ii = 0; ii < 4; ii++)
#pragma unroll
        for (int oo = 0; oo < 4; oo++) {
            float2 idv = Wp[i0 + ii][o0 + oo];
            wout[(i0 + ii) * 64 + o0 + oo] =
                make_float2(idv.x + accx[ii][oo], idv.y + accy[ii][oo]);
        }
}

// ---------------- input projection -------------------------------------------
__global__ void k_inproj(const float* __restrict__ x,
                         const float* __restrict__ in_w,
                         const float* __restrict__ in_b) {
    int idx = blockIdx.x * blockDim.x + threadIdx.x;
    int c   = idx & 63;
    int pix = idx >> 6;
    int n = pix & 255;
    int m = (pix >> 8) & 255;
    const float* xp = x + (size_t)pix * 3;
    float pm = -1.0f + ((float)m + 0.5f) * (2.0f / 256.0f);
    float pn = -1.0f + ((float)n + 0.5f) * (2.0f / 256.0f);
    float acc = in_b[c];
    acc += xp[0] * in_w[0 * WID + c];
    acc += xp[1] * in_w[1 * WID + c];
    acc += xp[2] * in_w[2 * WID + c];
    acc += pm    * in_w[3 * WID + c];
    acc += pn    * in_w[4 * WID + c];
    g_h[idx] = acc;
}

// ---------------- forward DFT along n (h -> T1)  [parity + tw recurrence] -----
__global__ void k_f1() {
    int bm = blockIdx.x;
    __shared__ float2 tw[256];
    __shared__ float  Es[64][64];          // 16 KB
    __shared__ float  Os[64][64];          // 16 KB
    int tid = threadIdx.x;
    tw[tid] = g_tw[tid];
    int ky = tid >> 4, cg = tid & 15;
    const float(*src)[64] = (ky & 1) ? Os : Es;
    const float4* hp4 = (const float4*)(g_h + (size_t)bm * NDIM * WID);
    float ar[4] = {0.f, 0.f, 0.f, 0.f}, ai[4] = {0.f, 0.f, 0.f, 0.f};
    for (int ch = 0; ch < 2; ch++) {
        int n0 = ch * 64;
        __syncthreads();
#pragma unroll
        for (int i = 0; i < 4; i++) {
            int f = tid + i * 256;
            int row = f >> 4, col4 = f & 15;
            float4 v0 = hp4[(size_t)(n0 + row) * 16 + col4];
            float4 v1 = hp4[(size_t)(n0 + 128 + row) * 16 + col4];
            float4 e, o;
            e.x = v0.x + v1.x; e.y = v0.y + v1.y;
            e.z = v0.z + v1.z; e.w = v0.w + v1.w;
            o.x = v0.x - v1.x; o.y = v0.y - v1.y;
            o.z = v0.z - v1.z; o.w = v0.w - v1.w;
            *(float4*)&Es[row][col4 * 4] = e;
            *(float4*)&Os[row][col4 * 4] = o;
        }
        __syncthreads();
        float2 wst = tw[ky];
        for (int nb = 0; nb < 4; nb++) {
            float2 t = tw[(ky * (n0 + nb * 16)) & 255];   // exact resync
#pragma unroll
            for (int ni = 0; ni < 16; ni++) {
                int nn = nb * 16 + ni;
                float4 hv = *(const float4*)&src[nn][cg * 4];
                ar[0] += hv.x * t.x; ai[0] -= hv.x * t.y;
                ar[1] += hv.y * t.x; ai[1] -= hv.y * t.y;
                ar[2] += hv.z * t.x; ai[2] -= hv.z * t.y;
                ar[3] += hv.w * t.x; ai[3] -= hv.w * t.y;
                t = cmul(t, wst);
            }
        }
    }
    float4* op = (float4*)(g_t1 + (size_t)bm * MODES * WID + ky * 64 + cg * 4);
    op[0] = make_float4(ar[0], ai[0], ar[1], ai[1]);
    op[1] = make_float4(ar[2], ai[2], ar[3], ai[3]);
}

// ---------------- forward DFT along m (T1 -> X)  [parity + tw recurrence] -----
__global__ void k_f2() {
    int bi = blockIdx.x;
    int cchunk = bi & 7;
    int ky     = (bi >> 3) & 15;
    int b      = bi >> 7;
    __shared__ float2 tw[256];
    __shared__ float2 Es[64][8];
    __shared__ float2 Os[64][8];
    int tid = threadIdx.x;
    tw[tid] = g_tw[tid];
    int j = tid >> 3, cl = tid & 7;
    int c0 = cchunk * 8;
    int kx = (j < 16) ? j : (224 + j);
    const float2(*src)[8] = (j & 1) ? Os : Es;
    float ar = 0.f, ai = 0.f;
    for (int ch = 0; ch < 2; ch++) {
        int m0 = ch * 64;
        __syncthreads();
#pragma unroll
        for (int i = 0; i < 2; i++) {
            int k = tid + i * 256;
            int m = k >> 3, cc = k & 7;
            float2 a = g_t1[((size_t)((b * 256 + m0 + m) * 16 + ky)) * 64 + c0 + cc];
            float2 d = g_t1[((size_t)((b * 256 + m0 + 128 + m) * 16 + ky)) * 64 + c0 + cc];
            Es[m][cc] = make_float2(a.x + d.x, a.y + d.y);
            Os[m][cc] = make_float2(a.x - d.x, a.y - d.y);
        }
        __syncthreads();
        float2 wst = tw[kx & 255];
        for (int mb = 0; mb < 4; mb++) {
            float2 w = tw[(kx * (m0 + mb * 16)) & 255];
#pragma unroll
            for (int mi = 0; mi < 16; mi++) {
                int mm = mb * 16 + mi;
                float2 t = src[mm][cl];
                ar += t.x * w.x + t.y * w.y;           // T1 * conj(w)
                ai += t.y * w.x - t.x * w.y;
                w = cmul(w, wst);
            }
        }
    }
    int p = (j < 16) ? (j * 16 + ky) : (256 + (j - 16) * 16 + ky);
    g_X[((size_t)p * 8 + b) * WID + c0 + cl] = make_float2(ar, ai);
}

// ---------------- spectral mixing (X -> Y)  [register-tiled, split planes] ----
// thread = (p2 = i-half, bh = b-half, o). 44 KB static smem.
__global__ void k_mix(int layer) {
    int p = blockIdx.x;
    __shared__ float2 W[64][64];      // 32 KB [i][o]
    __shared__ float  Xr[64][8];      //  2 KB [i][b]
    __shared__ float  Xi[64][8];      //  2 KB
    __shared__ float  redr[2][512];   //  4 KB
    __shared__ float  redi[2][512];   //  4 KB
    int tid = threadIdx.x;
    const float2* wp = g_W + ((size_t)layer * 512 + p) * 4096;
    for (int k = tid; k < 4096; k += 256)
        W[k >> 6][k & 63] = wp[k];
    for (int k = tid; k < 512; k += 256) {
        float2 v = g_X[(size_t)p * 512 + k];   // k = b*64 + c
        Xr[k & 63][k >> 6] = v.x;
        Xi[k & 63][k >> 6] = v.y;
    }
    __syncthreads();
    int o = tid & 63, bh = (tid >> 6) & 1, p2 = tid >> 7;
    float ar[4] = {0.f, 0.f, 0.f, 0.f}, ai_[4] = {0.f, 0.f, 0.f, 0.f};
#pragma unroll 8
    for (int ii = 0; ii < 32; ii++) {
        int i = p2 * 32 + ii;
        float2 wv = W[i][o];
        float4 xr = *(const float4*)&Xr[i][bh * 4];
        float4 xi = *(const float4*)&Xi[i][bh * 4];
        ar[0] += xr.x * wv.x - xi.x * wv.y;  ai_[0] += xr.x * wv.y + xi.x * wv.x;
        ar[1] += xr.y * wv.x - xi.y * wv.y;  ai_[1] += xr.y * wv.y + xi.y * wv.x;
        ar[2] += xr.z * wv.x - xi.z * wv.y;  ai_[2] += xr.z * wv.y + xi.z * wv.x;
        ar[3] += xr.w * wv.x - xi.w * wv.y;  ai_[3] += xr.w * wv.y + xi.w * wv.x;
    }
#pragma unroll
    for (int bb = 0; bb < 4; bb++) {
        redr[p2][(bh * 4 + bb) * 64 + o] = ar[bb];
        redi[p2][(bh * 4 + bb) * 64 + o] = ai_[bb];
    }
    __syncthreads();
    for (int k = tid; k < 512; k += 256) {
        g_Y[(size_t)p * 512 + k] =
            make_float2(redr[0][k] + redr[1][k], redi[0][k] + redi[1][k]);
    }
}

// ---------------- inverse DFT along kx (Y -> G)  [pairing + tw recurrence] ----
__global__ void k_i1() {
    int bi = blockIdx.x;
    int quad = bi & 3;
    int ky   = (bi >> 2) & 15;
    int b    = bi >> 6;
    __shared__ float2 tw[256];
    __shared__ float2 Ys[32][64];
    int tid = threadIdx.x;
    tw[tid] = g_tw[tid];
    for (int k = tid; k < 2048; k += 256) {
        int j = k >> 6, o = k & 63;
        int half = j >> 4, jl = j & 15;
        int p = half * 256 + jl * 16 + ky;
        Ys[j][o] = g_Y[((size_t)p * 8 + b) * 64 + o];
    }
    __syncthreads();
    int o = tid & 63, msub = tid >> 6;
    for (int it = 0; it < 8; it++) {
        int m = quad * 32 + it * 4 + msub;         // 0..127
        float2 step = tw[(2 * m) & 255];
        float Er = 0.f, Ei = 0.f, Or = 0.f, Oi = 0.f;
        // even kx, low band: kx = 0,2,..,14  (Ys rows 0,2,..,14); start tw[0]=1
        float2 t = make_float2(1.f, 0.f);
#pragma unroll
        for (int jj = 0; jj < 8; jj++) {
            float2 v = Ys[2 * jj][o];
            Er += v.x * t.x - v.y * t.y;
            Ei += v.x * t.y + v.y * t.x;
            t = cmul(t, step);
        }
        // even kx, high band: kx = 240..254 (rows 16,18,..,30)
        t = tw[(240 * m) & 255];
#pragma unroll
        for (int jj = 8; jj < 16; jj++) {
            float2 v = Ys[2 * jj][o];
            Er += v.x * t.x - v.y * t.y;
            Ei += v.x * t.y + v.y * t.x;
            t = cmul(t, step);
        }
        // odd kx, low band: kx = 1,3,..,15 (rows 1,3,..,15); start tw[m]
        t = tw[m & 255];
#pragma unroll
        for (int jj = 0; jj < 8; jj++) {
            float2 v = Ys[2 * jj + 1][o];
            Or += v.x * t.x - v.y * t.y;
            Oi += v.x * t.y + v.y * t.x;
            t = cmul(t, step);
        }
        // odd kx, high band: kx = 241..255 (rows 17,19,..,31)
        t = tw[(241 * m) & 255];
#pragma unroll
        for (int jj = 8; jj < 16; jj++) {
            float2 v = Ys[2 * jj + 1][o];
            Or += v.x * t.x - v.y * t.y;
            Oi += v.x * t.y + v.y * t.x;
            t = cmul(t, step);
        }
        g_G[(((size_t)b * 256 + m) * 16 + ky) * 64 + o] =
            make_float2(Er + Or, Ei + Oi);
        g_G[(((size_t)b * 256 + m + 128) * 16 + ky) * 64 + o] =
            make_float2(Er - Or, Ei - Oi);
    }
}

// ---------------- i2: inverse DFT along n + bias + ReLU -----------------------
__global__ void k_i2(const float* __restrict__ lin_b, int layer) {
    int bm = blockIdx.x;
    __shared__ float2 tw[256];
    __shared__ float2 Gs[16][64];   // prescaled
    __shared__ float  lb[64];
    int tid = threadIdx.x;
    tw[tid] = g_tw[tid];
    for (int k = tid; k < 1024; k += 256) {
        int ky = k >> 6, o = k & 63;
        float s = (ky == 0 ? 1.0f : 2.0f) * (1.0f / 65536.0f);
        float2 v = g_G[(size_t)bm * 1024 + k];
        Gs[ky][o] = make_float2(v.x * s, v.y * s);
    }
    if (tid < 64) lb[tid] = lin_b[layer * 64 + tid];
    __syncthreads();
    int tx = tid & 15, ty = tid >> 4;
    int c0 = tx * 4;
    float lb0 = lb[c0], lb1 = lb[c0 + 1], lb2 = lb[c0 + 2], lb3 = lb[c0 + 3];
    float* hout = g_h + (size_t)bm * NDIM * WID;
#pragma unroll
    for (int k = 0; k < 8; k++) {
        int n = ty * 8 + k;                  // 0..127
        float E0 = 0.f, E1 = 0.f, E2 = 0.f, E3 = 0.f;
        float O0 = 0.f, O1 = 0.f, O2 = 0.f, O3 = 0.f;
#pragma unroll
        for (int ky = 0; ky < 16; ky += 2) {
            float2 te = tw[(ky * n) & 255];
            float4 ae = *(const float4*)&Gs[ky][c0];
            float4 be = *(const float4*)&Gs[ky][c0 + 2];
            E0 += ae.x * te.x - ae.y * te.y;
            E1 += ae.z * te.x - ae.w * te.y;
            E2 += be.x * te.x - be.y * te.y;
            E3 += be.z * te.x - be.w * te.y;
            float2 to = tw[((ky + 1) * n) & 255];
            float4 ao = *(const float4*)&Gs[ky + 1][c0];
            float4 bo = *(const float4*)&Gs[ky + 1][c0 + 2];
            O0 += ao.x * to.x - ao.y * to.y;
            O1 += ao.z * to.x - ao.w * to.y;
            O2 += bo.x * to.x - bo.y * to.y;
            O3 += bo.z * to.x - bo.w * to.y;
        }
        float4 r0, r1;
        r0.x = fmaxf(E0 + O0 + lb0, 0.f);
        r0.y = fmaxf(E1 + O1 + lb1, 0.f);
        r0.z = fmaxf(E2 + O2 + lb2, 0.f);
        r0.w = fmaxf(E3 + O3 + lb3, 0.f);
        r1.x = fmaxf(E0 - O0 + lb0, 0.f);
        r1.y = fmaxf(E1 - O1 + lb1, 0.f);
        r1.z = fmaxf(E2 - O2 + lb2, 0.f);
        r1.w = fmaxf(E3 - O3 + lb3, 0.f);
        *(float4*)&hout[(size_t)n * WID + c0] = r0;
        *(float4*)&hout[(size_t)(n + 128) * WID + c0] = r1;
    }
}

// ---------------- output head: relu(h@W1+b1)@W2+b2 ----------------------------
__global__ void k_out(const float* __restrict__ out1_w,
                      const float* __restrict__ out1_b,
                      const float* __restrict__ out2_w,
                      const float* __restrict__ out2_b,
                      float* __restrict__ out) {
    int bm = blockIdx.x;
    __shared__ float hs [32][65];
    __shared__ float w1s[64][128];
    __shared__ float b1s[128];
    __shared__ float w2s[128];
    int tid = threadIdx.x;
    for (int k = tid; k < 8192; k += 256) w1s[k >> 7][k & 127] = out1_w[k];
    if (tid < 128) { b1s[tid] = out1_b[tid]; w2s[tid] = out2_w[tid]; }
    float b2 = out2_b[0];
    const float* hp = g_h + (size_t)bm * NDIM * WID;
    float* op = out + (size_t)bm * NDIM;
    int tx = tid & 31, ty = tid >> 5;
    for (int rnd = 0; rnd < 8; rnd++) {
        __syncthreads();
        for (int k = tid; k < 2048; k += 256)
            hs[k >> 6][k & 63] = hp[(size_t)rnd * 2048 + k];
        __syncthreads();
        float acc[4][4];
#pragma unroll
        for (int k = 0; k < 4; k++)
#pragma unroll
            for (int q = 0; q < 4; q++) acc[k][q] = b1s[tx * 4 + q];
#pragma unroll
        for (int j = 0; j < 64; j++) {
            float4 w4 = *(const float4*)&w1s[j][tx * 4];
#pragma unroll
            for (int k = 0; k < 4; k++) {
                float hv = hs[ty * 4 + k][j];
                acc[k][0] += hv * w4.x;
                acc[k][1] += hv * w4.y;
                acc[k][2] += hv * w4.z;
                acc[k][3] += hv * w4.w;
            }
        }
#pragma unroll
        for (int k = 0; k < 4; k++) {
            float part = fmaxf(acc[k][0], 0.f) * w2s[tx * 4 + 0]
                       + fmaxf(acc[k][1], 0.f) * w2s[tx * 4 + 1]
                       + fmaxf(acc[k][2], 0.f) * w2s[tx * 4 + 2]
                       + fmaxf(acc[k][3], 0.f) * w2s[tx * 4 + 3];
#pragma unroll
            for (int off = 16; off > 0; off >>= 1)
                part += __shfl_xor_sync(0xffffffffu, part, off);
            if (tx == 0) op[rnd * 32 + ty * 4 + k] = part + b2;
        }
    }
}

// ---------------- launch ------------------------------------------------------
extern "C" void kernel_launch(void* const* d_in, const int* in_sizes, int n_in,
                              void* d_out, int out_size) {
    const float* x      = (const float*)d_in[0];
    const float* in_w   = (const float*)d_in[1];
    const float* in_b   = (const float*)d_in[2];
    const float* fw1    = (const float*)d_in[3];
    const float* fw2    = (const float*)d_in[4];
    const float* lin_w  = (const float*)d_in[5];
    const float* lin_b  = (const float*)d_in[6];
    const float* out1_w = (const float*)d_in[7];
    const float* out1_b = (const float*)d_in[8];
    const float* out2_w = (const float*)d_in[9];
    const float* out2_b = (const float*)d_in[10];
    float* out = (float*)d_out;

    k_twiddle<<<1, 256>>>();
    k_wfold<<<NLAYERS * 512, 256>>>(fw1, fw2, lin_w);
    k_inproj<<<(BATCH * MDIM * NDIM * WID) / 256, 256>>>(x, in_w, in_b);
    for (int l = 0; l < NLAYERS; l++) {
        k_f1 <<<BATCH * MDIM, 256>>>();
        k_f2 <<<BATCH * MODES * 8, 256>>>();
        k_mix<<<512, 256>>>(l);
        k_i1 <<<BATCH * MODES * 4, 256>>>();
        k_i2 <<<BATCH * MDIM, 256>>>(lin_b, l);
    }
    k_out<<<BATCH * MDIM, 256>>>(out1_w, out1_b, out2_w, out2_b, out);
}